// round 13
// baseline (speedup 1.0000x reference)
#include <cuda_runtime.h>
#include <cuda_fp16.h>
#include <math.h>
#include <stdint.h>

#define N_CI    2048
#define N_EL    524288          // 8192 * 64
#define NSEG    8
#define KQ      1024            // K rows per segment/split
#define KC      32
#define NCH     (KQ / KC)       // 32 chunks
#define CO_LD   72              // Co tile row stride (halfs), n-tile 64
#define A_LD    40              // A tile row stride (halfs)

__device__ __align__(16) float g_y[N_EL];
__device__ __align__(16) __half g_zT[64 * 8192];      // [m][r] = y*sc fp16
__device__ __align__(16) __half g_scT[64 * 8192];
__device__ __align__(16) __half g_biT[64 * 8192];
__device__ __align__(16) float g_part[NSEG * 3 * N_EL];   // D,E,F per split
__device__ float g_psum[N_CI];
__device__ float g_psq[N_CI];
__device__ float g_stats[2];

__device__ __forceinline__ float gelu_tanh(float v) {
    const float c = 0.7978845608028654f;
    float t = tanhf(c * (v + 0.044715f * v * v * v));
    return 0.5f * v * (1.0f + t);
}

// ===========================================================================
// K1 (per segment of 256 capsules): y = gelu(Wi @ x); LN partial sums.
// ===========================================================================
__global__ void __launch_bounds__(256) k1_capsule(const float* __restrict__ x,
                                                  const float* __restrict__ Wi,
                                                  int seg) {
    __shared__ float4 xs4[64];
    __shared__ float s_sum, s_sq;
    int tid = threadIdx.x;
    int i = seg * 256 + blockIdx.x;
    if (tid == 0) { s_sum = 0.f; s_sq = 0.f; }
    {
        int k = tid >> 2, m = tid & 3;
        ((float*)xs4)[tid] = x[(size_t)i * 256 + m * 64 + k];
    }
    __syncthreads();

    int w = tid >> 5, lane = tid & 31;
    int l = lane & 3, kq = lane >> 2;
    const float4* wbase = (const float4*)(Wi + (size_t)i * 65536);
    float ls = 0.f, ls2 = 0.f;

    #pragma unroll 1
    for (int jj = 0; jj < 8; jj += 2) {
        int j0 = w * 8 + jj;
        const float4* wp0 = wbase + (size_t)j0 * 256 + lane;
        const float4* wp1 = wp0 + 256;
        float acc0 = 0.f, acc1 = 0.f;
        #pragma unroll
        for (int r = 0; r < 8; r++) {
            float4 wv0 = wp0[r * 32];
            float4 wv1 = wp1[r * 32];
            float4 xv = xs4[r * 8 + kq];
            acc0 = fmaf(wv0.x, xv.x, acc0); acc0 = fmaf(wv0.y, xv.y, acc0);
            acc0 = fmaf(wv0.z, xv.z, acc0); acc0 = fmaf(wv0.w, xv.w, acc0);
            acc1 = fmaf(wv1.x, xv.x, acc1); acc1 = fmaf(wv1.y, xv.y, acc1);
            acc1 = fmaf(wv1.z, xv.z, acc1); acc1 = fmaf(wv1.w, xv.w, acc1);
        }
        acc0 += __shfl_xor_sync(0xffffffffu, acc0, 4);
        acc0 += __shfl_xor_sync(0xffffffffu, acc0, 8);
        acc0 += __shfl_xor_sync(0xffffffffu, acc0, 16);
        acc1 += __shfl_xor_sync(0xffffffffu, acc1, 4);
        acc1 += __shfl_xor_sync(0xffffffffu, acc1, 8);
        acc1 += __shfl_xor_sync(0xffffffffu, acc1, 16);
        float g0 = gelu_tanh(acc0);
        float g1 = gelu_tanh(acc1);
        if (lane < 4) {
            float* yp = &g_y[((size_t)i * 4 + l) * 64 + j0];
            yp[0] = g0; yp[1] = g1;
            ls += g0 + g1;
            ls2 += g0 * g0 + g1 * g1;
        }
    }
    if (lane < 4) {
        atomicAdd(&s_sum, ls);
        atomicAdd(&s_sq, ls2);
    }
    __syncthreads();
    if (tid == 0) { g_psum[i] = s_sum; g_psq[i] = s_sq; }
}

// ===========================================================================
// K2: reduce partials -> mu, rsig (1 CTA, fp64)
// ===========================================================================
__global__ void k2_stats() {
    __shared__ double sh[256], sh2[256];
    int tid = threadIdx.x;
    double a = 0.0, b = 0.0;
    for (int i = tid; i < N_CI; i += 256) {
        a += (double)g_psum[i];
        b += (double)g_psq[i];
    }
    sh[tid] = a; sh2[tid] = b;
    __syncthreads();
    for (int s = 128; s > 0; s >>= 1) {
        if (tid < s) { sh[tid] += sh[tid + s]; sh2[tid] += sh2[tid + s]; }
        __syncthreads();
    }
    if (tid == 0) {
        double mu = sh[0] / (double)N_EL;
        double var = sh2[0] / (double)N_EL - mu * mu;
        g_stats[0] = (float)mu;
        g_stats[1] = (float)(1.0 / sqrt(var + 1e-6));
    }
}

// ===========================================================================
// k0: transpose sc, bi (fp32 [r][m]) -> fp16 [m][r]. No dependencies.
// ===========================================================================
__global__ void __launch_bounds__(256) k0_scbiT(const float* __restrict__ sc,
                                                 const float* __restrict__ bi) {
    __shared__ __half shs[64 * 65];
    __shared__ __half shb[64 * 65];
    int tid = threadIdx.x;
    int r0 = blockIdx.x * 64;

    #pragma unroll
    for (int it = 0; it < 16; it++) {
        int idx = tid + it * 256;
        int r = idx >> 6, m = idx & 63;
        size_t gi = (size_t)(r0 + r) * 64 + m;
        shs[m * 65 + r] = __float2half(sc[gi]);
        shb[m * 65 + r] = __float2half(bi[gi]);
    }
    __syncthreads();
    int w = tid >> 5, lane = tid & 31;
    #pragma unroll 1
    for (int m = w; m < 64; m += 8) {
        __half2 ps, pb;
        ps.x = shs[m * 65 + lane * 2]; ps.y = shs[m * 65 + lane * 2 + 1];
        pb.x = shb[m * 65 + lane * 2]; pb.y = shb[m * 65 + lane * 2 + 1];
        *((__half2*)(g_scT + (size_t)m * 8192 + r0) + lane) = ps;
        *((__half2*)(g_biT + (size_t)m * 8192 + r0) + lane) = pb;
    }
}

// ===========================================================================
// k1zT (per segment): z = y*sc -> fp16 transposed [m][r]. grid 16.
// ===========================================================================
__global__ void __launch_bounds__(256) k1zT(const float* __restrict__ sc, int seg) {
    __shared__ __half sh[64 * 65];
    int tid = threadIdx.x;
    int r0 = seg * 1024 + blockIdx.x * 64;

    #pragma unroll
    for (int it = 0; it < 16; it++) {
        int idx = tid + it * 256;
        int r = idx >> 6, m = idx & 63;
        size_t gi = (size_t)(r0 + r) * 64 + m;
        sh[m * 65 + r] = __float2half(g_y[gi] * sc[gi]);
    }
    __syncthreads();
    int w = tid >> 5, lane = tid & 31;
    #pragma unroll 1
    for (int m = w; m < 64; m += 8) {
        __half2 p;
        p.x = sh[m * 65 + lane * 2];
        p.y = sh[m * 65 + lane * 2 + 1];
        *((__half2*)(g_zT + (size_t)m * 8192 + r0) + lane) = p;
    }
}

// ===========================================================================
// mma helpers
// ===========================================================================
__device__ __forceinline__ void ldsm4(uint32_t& r0, uint32_t& r1, uint32_t& r2,
                                      uint32_t& r3, const void* p) {
    uint32_t a = (uint32_t)__cvta_generic_to_shared(p);
    asm volatile("ldmatrix.sync.aligned.m8n8.x4.shared.b16 {%0,%1,%2,%3}, [%4];"
                 : "=r"(r0), "=r"(r1), "=r"(r2), "=r"(r3) : "r"(a));
}
__device__ __forceinline__ void ldsm4t(uint32_t& r0, uint32_t& r1, uint32_t& r2,
                                       uint32_t& r3, const void* p) {
    uint32_t a = (uint32_t)__cvta_generic_to_shared(p);
    asm volatile("ldmatrix.sync.aligned.m8n8.x4.trans.shared.b16 {%0,%1,%2,%3}, [%4];"
                 : "=r"(r0), "=r"(r1), "=r"(r2), "=r"(r3) : "r"(a));
}
__device__ __forceinline__ void mma16816(float* d, uint32_t a0, uint32_t a1,
                                         uint32_t a2, uint32_t a3,
                                         uint32_t b0, uint32_t b1) {
    asm volatile(
        "mma.sync.aligned.m16n8k16.row.col.f32.f16.f16.f32 "
        "{%0,%1,%2,%3}, {%4,%5,%6,%7}, {%8,%9}, {%0,%1,%2,%3};"
        : "+f"(d[0]), "+f"(d[1]), "+f"(d[2]), "+f"(d[3])
        : "r"(a0), "r"(a1), "r"(a2), "r"(a3), "r"(b0), "r"(b1));
}

// ===========================================================================
// k3t (per split s): triple GEMM sharing one Co stream.
// D/E/F[n,m] = sum_k {zT,scT,biT}[m,k]*Co[k,n], k in [s*1024,(s+1)*1024).
// Grid 128 col-tiles (n=64). 192 threads = 6 warps: (mgrp 0..2) x (ngrp 0..1),
// warp tile m64 x n32. Co: warps 0-1 LDG fp32 -> cvt fp16 -> STS (reg
// prefetch 1 chunk ahead). A (192 rows x 32k fp16): threads 64-191 cp.async.
// ===========================================================================
__global__ void __launch_bounds__(192, 2) k3t_gemm(const float* __restrict__ Co,
                                                   int s) {
    __shared__ __align__(16) __half co_s[2][KC][CO_LD];    // 9.2 KB
    __shared__ __align__(16) __half a_s[2][192][A_LD];     // 30.7 KB
    int tid = threadIdx.x, w = tid >> 5, lane = tid & 31;
    int mgrp = w >> 1, ngrp = w & 1;
    int colbase = blockIdx.x * 64;
    int k_org = s * KQ;

    // Co staging map (threads 0-63): f4 id = t + 64j -> row = id/16, c4 = id%16
    float4 cr[8];
    const float* csrc = Co + (size_t)k_org * 8192 + colbase;
    auto LOADC = [&](int ch) {
        if (tid < 64) {
            const float* base = csrc + (size_t)ch * KC * 8192;
            #pragma unroll
            for (int j = 0; j < 8; j++) {
                int id = tid + 64 * j;
                cr[j] = __ldg((const float4*)(base + (size_t)(id >> 4) * 8192) + (id & 15));
            }
        }
    };
    auto STOREC = [&](int buf) {
        if (tid < 64) {
            #pragma unroll
            for (int j = 0; j < 8; j++) {
                int id = tid + 64 * j;
                uint32_t p0, p1;
                asm("cvt.rn.f16x2.f32 %0, %1, %2;" : "=r"(p0) : "f"(cr[j].y), "f"(cr[j].x));
                asm("cvt.rn.f16x2.f32 %0, %1, %2;" : "=r"(p1) : "f"(cr[j].w), "f"(cr[j].z));
                *(uint2*)&co_s[buf][id >> 4][(id & 15) * 4] = make_uint2(p0, p1);
            }
        }
    };

    // A staging (threads 64-191): 6 cp.async of 16B each
    const __half* abase[6];
    uint32_t adst_off[6];
    {
        int u = tid - 64;
        #pragma unroll
        for (int j = 0; j < 6; j++) {
            int cid = u * 6 + j;            // 0..767
            int row = cid >> 2, qq = cid & 3;
            const __half* p = (row < 64) ? g_zT + (size_t)row * 8192
                            : (row < 128) ? g_scT + (size_t)(row - 64) * 8192
                                          : g_biT + (size_t)(row - 128) * 8192;
            abase[j] = p + k_org + qq * 8;
            adst_off[j] = (uint32_t)(row * A_LD + qq * 8) * 2u;
        }
    }
    uint32_t a_sb = (uint32_t)__cvta_generic_to_shared(&a_s[0][0][0]);
    const uint32_t A_BUF_BYTES = 192 * A_LD * 2;
    auto LOADA = [&](int ch, int buf) {
        if (tid >= 64) {
            #pragma unroll
            for (int j = 0; j < 6; j++)
                asm volatile("cp.async.ca.shared.global [%0], [%1], 16;"
                             :: "r"(a_sb + buf * A_BUF_BYTES + adst_off[j]),
                                "l"(abase[j] + ch * KC) : "memory");
        }
    };

    float d[4][4][4];
    #pragma unroll
    for (int mt = 0; mt < 4; mt++)
        #pragma unroll
        for (int nt = 0; nt < 4; nt++)
            #pragma unroll
            for (int v = 0; v < 4; v++) d[mt][nt][v] = 0.f;

    int q = lane >> 3, r8 = lane & 7;
    int arow = (q & 1) * 8 + r8, acol = (q >> 1) * 8;

    // prologue
    LOADC(0); STOREC(0); LOADA(0, 0);
    asm volatile("cp.async.commit_group;" ::: "memory");
    LOADC(1);
    asm volatile("cp.async.wait_group 0;" ::: "memory");
    __syncthreads();

    #pragma unroll 1
    for (int ch = 0; ch < NCH; ch++) {
        int buf = ch & 1;
        if (ch + 1 < NCH) LOADA(ch + 1, buf ^ 1);
        asm volatile("cp.async.commit_group;" ::: "memory");
        #pragma unroll
        for (int kk = 0; kk < 2; kk++) {
            uint32_t b[8];
            ldsm4t(b[0], b[1], b[2], b[3], &co_s[buf][kk * 16 + arow][ngrp * 32 + acol]);
            ldsm4t(b[4], b[5], b[6], b[7], &co_s[buf][kk * 16 + arow][ngrp * 32 + 16 + acol]);
            #pragma unroll
            for (int mt = 0; mt < 4; mt++) {
                uint32_t a0, a1, a2, a3;
                ldsm4(a0, a1, a2, a3, &a_s[buf][mgrp * 64 + mt * 16 + arow][kk * 16 + acol]);
                mma16816(d[mt][0], a0, a1, a2, a3, b[0], b[1]);
                mma16816(d[mt][1], a0, a1, a2, a3, b[2], b[3]);
                mma16816(d[mt][2], a0, a1, a2, a3, b[4], b[5]);
                mma16816(d[mt][3], a0, a1, a2, a3, b[6], b[7]);
            }
        }
        __syncthreads();                 // everyone done reading buf
        if (ch + 1 < NCH) {
            STOREC(buf ^ 1);             // fp16 Co into other buffer
            if (ch + 2 < NCH) LOADC(ch + 2);
        }
        asm volatile("cp.async.wait_group 0;" ::: "memory");
        __syncthreads();                 // buf^1 (Co STS + A cp.async) ready
    }

    // epilogue: partial for (split s, matrix mgrp)
    float* pb = g_part + (size_t)(s * 3 + mgrp) * N_EL;
    int er = lane >> 2, ec = (lane & 3) * 2;
    #pragma unroll
    for (int mt = 0; mt < 4; mt++) {
        #pragma unroll
        for (int nt = 0; nt < 4; nt++) {
            int n = colbase + ngrp * 32 + nt * 8 + ec;
            int m = mt * 16 + er;
            pb[(size_t)n * 64 + m]           = d[mt][nt][0];
            pb[(size_t)(n + 1) * 64 + m]     = d[mt][nt][1];
            pb[(size_t)n * 64 + m + 8]       = d[mt][nt][2];
            pb[(size_t)(n + 1) * 64 + m + 8] = d[mt][nt][3];
        }
    }
}

// ===========================================================================
// K4: out = rs*sum(D) - mu*rs*sum(E) + sum(F)
// ===========================================================================
__global__ void __launch_bounds__(256) k4_ep(float* __restrict__ out) {
    int idx = blockIdx.x * 256 + threadIdx.x;
    float mu = g_stats[0], rs = g_stats[1];
    float c2 = -mu * rs;
    float4 aD = make_float4(0.f, 0.f, 0.f, 0.f);
    float4 aE = aD, aF = aD;
    #pragma unroll
    for (int s = 0; s < NSEG; s++) {
        float4 dD = ((const float4*)(g_part + (size_t)(s * 3 + 0) * N_EL))[idx];
        float4 dE = ((const float4*)(g_part + (size_t)(s * 3 + 1) * N_EL))[idx];
        float4 dF = ((const float4*)(g_part + (size_t)(s * 3 + 2) * N_EL))[idx];
        aD.x += dD.x; aD.y += dD.y; aD.z += dD.z; aD.w += dD.w;
        aE.x += dE.x; aE.y += dE.y; aE.z += dE.z; aE.w += dE.w;
        aF.x += dF.x; aF.y += dF.y; aF.z += dF.z; aF.w += dF.w;
    }
    float4 o;
    o.x = rs * aD.x + c2 * aE.x + aF.x;
    o.y = rs * aD.y + c2 * aE.y + aF.y;
    o.z = rs * aD.z + c2 * aE.z + aF.z;
    o.w = rs * aD.w + c2 * aE.w + aF.w;
    ((float4*)out)[idx] = o;
}

// ===========================================================================
// host: two-stream pipeline (fork/join via events; capture-safe pattern)
// ===========================================================================
struct K3Streams {
    cudaStream_t s2;
    cudaEvent_t eFork, eSeg[NSEG], eJoin;
    K3Streams() {
        cudaStreamCreateWithFlags(&s2, cudaStreamNonBlocking);
        cudaEventCreateWithFlags(&eFork, cudaEventDisableTiming);
        for (int i = 0; i < NSEG; i++)
            cudaEventCreateWithFlags(&eSeg[i], cudaEventDisableTiming);
        cudaEventCreateWithFlags(&eJoin, cudaEventDisableTiming);
    }
};
static K3Streams g_ks;

extern "C" void kernel_launch(void* const* d_in, const int* in_sizes, int n_in,
                              void* d_out, int out_size) {
    const float* x  = (const float*)d_in[0];
    const float* Wi = (const float*)d_in[1];
    const float* sc = (const float*)d_in[2];
    const float* bi = (const float*)d_in[3];
    const float* Co = (const float*)d_in[4];
    float* out = (float*)d_out;

    // fork side stream off the main (captured) stream
    cudaEventRecord(g_ks.eFork, 0);
    cudaStreamWaitEvent(g_ks.s2, g_ks.eFork, 0);
    k0_scbiT<<<128, 256, 0, g_ks.s2>>>(sc, bi);

    for (int s = 0; s < NSEG; s++) {
        k1_capsule<<<256, 256>>>(x, Wi, s);
        cudaEventRecord(g_ks.eSeg[s], 0);
        cudaStreamWaitEvent(g_ks.s2, g_ks.eSeg[s], 0);
        k1zT<<<16, 256, 0, g_ks.s2>>>(sc, s);
        k3t_gemm<<<128, 192, 0, g_ks.s2>>>(Co, s);
    }
    k2_stats<<<1, 256>>>();

    // join
    cudaEventRecord(g_ks.eJoin, g_ks.s2);
    cudaStreamWaitEvent(0, g_ks.eJoin, 0);
    k4_ep<<<512, 256>>>(out);
}

// round 14
// speedup vs baseline: 2.1115x; 2.1115x over previous
#include <cuda_runtime.h>
#include <cuda_fp16.h>
#include <math.h>
#include <stdint.h>

#define N_CI    2048
#define N_EL    524288          // 8192 * 64
#define KSPLIT  8
#define KQ      1024            // K per split
#define KC      32
#define NCH     (KQ / KC)       // 32 chunks
#define CO_LD   136             // Co tile row stride (fp16 elems)
#define YN_LD   40              // ynT tile row stride

__device__ __align__(16) float g_y[N_EL];
__device__ __align__(16) __half g_ynT[64 * 8192];         // [m][row], fp16
__device__ __align__(16) float g_part[KSPLIT * N_EL];
__device__ float g_psum[N_CI];
__device__ float g_psq[N_CI];
__device__ float g_stats[2];

__device__ __forceinline__ float gelu_tanh(float v) {
    const float c = 0.7978845608028654f;
    float t = tanhf(c * (v + 0.044715f * v * v * v));
    return 0.5f * v * (1.0f + t);
}

// ===========================================================================
// K1: y[i,l,j] = sum_{k,m} Wi[i,j,k,l,m] * x[i,m,k]; gelu; LN partials.
// (exact R10 version)
// ===========================================================================
__global__ void __launch_bounds__(256) k1_capsule(const float* __restrict__ x,
                                                  const float* __restrict__ Wi) {
    __shared__ float4 xs4[64];
    __shared__ float s_sum, s_sq;
    int tid = threadIdx.x;
    int i = blockIdx.x;
    if (tid == 0) { s_sum = 0.f; s_sq = 0.f; }
    {
        int k = tid >> 2, m = tid & 3;
        ((float*)xs4)[tid] = x[(size_t)i * 256 + m * 64 + k];
    }
    __syncthreads();

    int w = tid >> 5, lane = tid & 31;
    int l = lane & 3, kq = lane >> 2;
    const float4* wbase = (const float4*)(Wi + (size_t)i * 65536);
    float ls = 0.f, ls2 = 0.f;

    #pragma unroll 1
    for (int jj = 0; jj < 8; jj += 2) {
        int j0 = w * 8 + jj;
        const float4* wp0 = wbase + (size_t)j0 * 256 + lane;
        const float4* wp1 = wp0 + 256;
        float acc0 = 0.f, acc1 = 0.f;
        #pragma unroll
        for (int r = 0; r < 8; r++) {
            float4 wv0 = wp0[r * 32];
            float4 wv1 = wp1[r * 32];
            float4 xv = xs4[r * 8 + kq];
            acc0 = fmaf(wv0.x, xv.x, acc0); acc0 = fmaf(wv0.y, xv.y, acc0);
            acc0 = fmaf(wv0.z, xv.z, acc0); acc0 = fmaf(wv0.w, xv.w, acc0);
            acc1 = fmaf(wv1.x, xv.x, acc1); acc1 = fmaf(wv1.y, xv.y, acc1);
            acc1 = fmaf(wv1.z, xv.z, acc1); acc1 = fmaf(wv1.w, xv.w, acc1);
        }
        acc0 += __shfl_xor_sync(0xffffffffu, acc0, 4);
        acc0 += __shfl_xor_sync(0xffffffffu, acc0, 8);
        acc0 += __shfl_xor_sync(0xffffffffu, acc0, 16);
        acc1 += __shfl_xor_sync(0xffffffffu, acc1, 4);
        acc1 += __shfl_xor_sync(0xffffffffu, acc1, 8);
        acc1 += __shfl_xor_sync(0xffffffffu, acc1, 16);
        float g0 = gelu_tanh(acc0);
        float g1 = gelu_tanh(acc1);
        if (lane < 4) {
            float* yp = &g_y[((size_t)i * 4 + l) * 64 + j0];
            yp[0] = g0; yp[1] = g1;
            ls += g0 + g1;
            ls2 += g0 * g0 + g1 * g1;
        }
    }
    if (lane < 4) {
        atomicAdd(&s_sum, ls);
        atomicAdd(&s_sq, ls2);
    }
    __syncthreads();
    if (tid == 0) { g_psum[i] = s_sum; g_psq[i] = s_sq; }
}

// ===========================================================================
// K2: reduce partials -> mu, rsig (1 CTA, fp64)
// ===========================================================================
__global__ void k2_stats() {
    __shared__ double sh[256], sh2[256];
    int tid = threadIdx.x;
    double a = 0.0, b = 0.0;
    for (int i = tid; i < N_CI; i += 256) {
        a += (double)g_psum[i];
        b += (double)g_psq[i];
    }
    sh[tid] = a; sh2[tid] = b;
    __syncthreads();
    for (int s = 128; s > 0; s >>= 1) {
        if (tid < s) { sh[tid] += sh[tid + s]; sh2[tid] += sh2[tid + s]; }
        __syncthreads();
    }
    if (tid == 0) {
        double mu = sh[0] / (double)N_EL;
        double var = sh2[0] / (double)N_EL - mu * mu;
        g_stats[0] = (float)mu;
        g_stats[1] = (float)(1.0 / sqrt(var + 1e-6));
    }
}

// ===========================================================================
// K2b: normalize -> fp16, transpose into ynT[m][row].
// ===========================================================================
__global__ void __launch_bounds__(256) k2b_normT(const float* __restrict__ sc,
                                                  const float* __restrict__ bi) {
    __shared__ __half sh[64 * 65];
    int tid = threadIdx.x;
    int r0 = blockIdx.x * 64;
    float mu = g_stats[0], rs = g_stats[1];

    #pragma unroll
    for (int it = 0; it < 16; it++) {
        int idx = tid + it * 256;
        int r = idx >> 6, m = idx & 63;
        size_t gi = (size_t)(r0 + r) * 64 + m;
        float val = (g_y[gi] - mu) * rs * sc[gi] + bi[gi];
        sh[m * 65 + r] = __float2half(val);
    }
    __syncthreads();

    int w = tid >> 5, lane = tid & 31;
    #pragma unroll 1
    for (int m = w; m < 64; m += 8) {
        __half2 p;
        p.x = sh[m * 65 + lane * 2];
        p.y = sh[m * 65 + lane * 2 + 1];
        *((__half2*)(g_ynT + (size_t)m * 8192 + r0) + lane) = p;
    }
}

// ===========================================================================
// mma helpers (fp16 HMMA path)
// ===========================================================================
__device__ __forceinline__ void ldsm4(uint32_t& r0, uint32_t& r1, uint32_t& r2,
                                      uint32_t& r3, const void* p) {
    uint32_t a = (uint32_t)__cvta_generic_to_shared(p);
    asm volatile("ldmatrix.sync.aligned.m8n8.x4.shared.b16 {%0,%1,%2,%3}, [%4];"
                 : "=r"(r0), "=r"(r1), "=r"(r2), "=r"(r3) : "r"(a));
}
__device__ __forceinline__ void ldsm4t(uint32_t& r0, uint32_t& r1, uint32_t& r2,
                                       uint32_t& r3, const void* p) {
    uint32_t a = (uint32_t)__cvta_generic_to_shared(p);
    asm volatile("ldmatrix.sync.aligned.m8n8.x4.trans.shared.b16 {%0,%1,%2,%3}, [%4];"
                 : "=r"(r0), "=r"(r1), "=r"(r2), "=r"(r3) : "r"(a));
}
__device__ __forceinline__ void mma16816(float* d, uint32_t a0, uint32_t a1,
                                         uint32_t a2, uint32_t a3,
                                         uint32_t b0, uint32_t b1) {
    asm volatile(
        "mma.sync.aligned.m16n8k16.row.col.f32.f16.f16.f32 "
        "{%0,%1,%2,%3}, {%4,%5,%6,%7}, {%8,%9}, {%0,%1,%2,%3};"
        : "+f"(d[0]), "+f"(d[1]), "+f"(d[2]), "+f"(d[3])
        : "r"(a0), "r"(a1), "r"(a2), "r"(a3), "r"(b0), "r"(b1));
}

// ===========================================================================
// K3: out_part[n,m] = sum_k ynT[m,k]*Co[k,n] via mma.sync fp16.
// Grid (64 col-tiles x 128 n, 8 k-splits x 1024). 256 threads (8 warps),
// 2 CTAs/SM -> 16 warps/SM. Warp grid 2(m-group of 32) x 4(n-group of 32);
// warp tile m32 x n32, acc 32 regs. Same smem tiles as R10, staging spread
// over 256 threads. Double-buffered, 1-chunk register prefetch.
// ===========================================================================
__global__ void __launch_bounds__(256, 2) k3_gemm(const float* __restrict__ Co) {
    __shared__ __align__(16) __half co_s[2][KC][CO_LD];    // 17.4 KB
    __shared__ __align__(16) __half yn_s[2][64][YN_LD];    // 10.2 KB
    int tid = threadIdx.x, w = tid >> 5, lane = tid & 31;
    int wm = w >> 2, wn = w & 3;              // m-group (0..1), n-group (0..3)
    int colbase = blockIdx.x * 128;
    int k_org = blockIdx.y * KQ;

    // staging maps: Co 32x128 fp32 -> 64B/thread (4 float4, 8 thr/row);
    //               yn 64x32 fp16 -> 16B/thread (1 uint4, 4 thr/row)
    int ck = tid >> 3, cf4 = tid & 7;
    int ym = tid >> 2, yq = tid & 3;
    const float4* cptr = (const float4*)(Co + (size_t)(k_org + ck) * 8192 + colbase) + cf4;
    const __half* yptr = g_ynT + (size_t)ym * 8192 + k_org + yq * 8;

    float4 cr[4];
    uint4  yr;

    auto LOAD = [&](int ch) {
        const float4* p = cptr + (size_t)ch * KC * 2048;
        #pragma unroll
        for (int j = 0; j < 4; j++) cr[j] = __ldg(p + j * 8);
        yr = __ldg((const uint4*)(yptr + ch * KC));
    };
    auto STORE = [&](int buf) {
        #pragma unroll
        for (int j = 0; j < 4; j++) {
            uint32_t p0, p1;
            asm("cvt.rn.f16x2.f32 %0, %1, %2;" : "=r"(p0) : "f"(cr[j].y), "f"(cr[j].x));
            asm("cvt.rn.f16x2.f32 %0, %1, %2;" : "=r"(p1) : "f"(cr[j].w), "f"(cr[j].z));
            *(uint2*)&co_s[buf][ck][(cf4 + j * 8) * 4] = make_uint2(p0, p1);
        }
        *(uint4*)&yn_s[buf][ym][yq * 8] = yr;
    };

    float d[2][4][4];                         // [mt][nt][v]
    #pragma unroll
    for (int mt = 0; mt < 2; mt++)
        #pragma unroll
        for (int nt = 0; nt < 4; nt++)
            #pragma unroll
            for (int v = 0; v < 4; v++) d[mt][nt][v] = 0.f;

    int q = lane >> 3, r8 = lane & 7;
    int arow = (q & 1) * 8 + r8, acol = (q >> 1) * 8;

    LOAD(0); STORE(0);
    LOAD(1);
    __syncthreads();

    #pragma unroll 1
    for (int ch = 0; ch < NCH; ch++) {
        int buf = ch & 1;
        #pragma unroll
        for (int kk = 0; kk < 2; kk++) {
            uint32_t b[8];
            ldsm4t(b[0], b[1], b[2], b[3], &co_s[buf][kk * 16 + arow][wn * 32 + acol]);
            ldsm4t(b[4], b[5], b[6], b[7], &co_s[buf][kk * 16 + arow][wn * 32 + 16 + acol]);
            #pragma unroll
            for (int mt = 0; mt < 2; mt++) {
                uint32_t a0, a1, a2, a3;
                ldsm4(a0, a1, a2, a3, &yn_s[buf][wm * 32 + mt * 16 + arow][kk * 16 + acol]);
                mma16816(d[mt][0], a0, a1, a2, a3, b[0], b[1]);
                mma16816(d[mt][1], a0, a1, a2, a3, b[2], b[3]);
                mma16816(d[mt][2], a0, a1, a2, a3, b[4], b[5]);
                mma16816(d[mt][3], a0, a1, a2, a3, b[6], b[7]);
            }
        }
        __syncthreads();
        if (ch + 1 < NCH) {
            STORE(buf ^ 1);
            if (ch + 2 < NCH) LOAD(ch + 2);
        }
        __syncthreads();
    }

    // epilogue: write k-split partial
    float* pb = g_part + (size_t)blockIdx.y * N_EL;
    int er = lane >> 2, ec = (lane & 3) * 2;
    #pragma unroll
    for (int mt = 0; mt < 2; mt++) {
        #pragma unroll
        for (int nt = 0; nt < 4; nt++) {
            int n = colbase + wn * 32 + nt * 8 + ec;
            int m = wm * 32 + mt * 16 + er;
            pb[(size_t)n * 64 + m]           = d[mt][nt][0];
            pb[(size_t)(n + 1) * 64 + m]     = d[mt][nt][1];
            pb[(size_t)n * 64 + m + 8]       = d[mt][nt][2];
            pb[(size_t)(n + 1) * 64 + m + 8] = d[mt][nt][3];
        }
    }
}

// ===========================================================================
// K4: out = sum of 8 k-split partials (float4)
// ===========================================================================
__global__ void __launch_bounds__(256) k4_reduce(float* __restrict__ out) {
    int idx = blockIdx.x * 256 + threadIdx.x;
    float4 a = ((const float4*)g_part)[idx];
    #pragma unroll
    for (int s = 1; s < KSPLIT; s++) {
        float4 b = ((const float4*)(g_part + (size_t)s * N_EL))[idx];
        a.x += b.x; a.y += b.y; a.z += b.z; a.w += b.w;
    }
    ((float4*)out)[idx] = a;
}

extern "C" void kernel_launch(void* const* d_in, const int* in_sizes, int n_in,
                              void* d_out, int out_size) {
    const float* x  = (const float*)d_in[0];
    const float* Wi = (const float*)d_in[1];
    const float* sc = (const float*)d_in[2];
    const float* bi = (const float*)d_in[3];
    const float* Co = (const float*)d_in[4];
    float* out = (float*)d_out;

    k1_capsule<<<N_CI, 256>>>(x, Wi);
    k2_stats<<<1, 256>>>();
    k2b_normT<<<128, 256>>>(sc, bi);
    dim3 g3(64, KSPLIT);
    k3_gemm<<<g3, 256>>>(Co);
    k4_reduce<<<512, 256>>>(out);
}